// round 6
// baseline (speedup 1.0000x reference)
#include <cuda_runtime.h>

#define BB    16
#define NN    16384
#define NFPS  512
#define NREG  50
#define TOPK  4
#define NB    128
#define R2C   0.16f

typedef unsigned int u32;
typedef unsigned long long u64;

__device__ int g_fps_idx[BB][NFPS];
__device__ int g_counts[BB][NREG];
__device__ int g_top4[BB][TOPK];

// ---- packed f32x2 helpers (sm_100a) ---------------------------------------
__device__ __forceinline__ u64 pack2(float lo, float hi) {
    u64 r; asm("mov.b64 %0,{%1,%2};" : "=l"(r) : "f"(lo), "f"(hi)); return r;
}
__device__ __forceinline__ void unpack2(u64 v, float& lo, float& hi) {
    asm("mov.b64 {%0,%1},%2;" : "=f"(lo), "=f"(hi) : "l"(v));
}
__device__ __forceinline__ u64 add2(u64 a, u64 b) {
    u64 r; asm("add.rn.f32x2 %0,%1,%2;" : "=l"(r) : "l"(a), "l"(b)); return r;
}
__device__ __forceinline__ u64 mul2(u64 a, u64 b) {
    u64 r; asm("mul.rn.f32x2 %0,%1,%2;" : "=l"(r) : "l"(a), "l"(b)); return r;
}
__device__ __forceinline__ u64 fma2(u64 a, u64 b, u64 c) {
    u64 r; asm("fma.rn.f32x2 %0,%1,%2,%3;" : "=l"(r) : "l"(a), "l"(b), "l"(c)); return r;
}
__device__ __forceinline__ u64 umax64(u64 a, u64 b) { return a > b ? a : b; }

// ---- cluster / mbarrier helpers --------------------------------------------
__device__ __forceinline__ u32 smem_u32(const void* p) {
    return (u32)__cvta_generic_to_shared(p);
}
__device__ __forceinline__ u32 mapa_rank(u32 addr, u32 rank) {
    u32 r;
    asm("mapa.shared::cluster.u32 %0,%1,%2;" : "=r"(r) : "r"(addr), "r"(rank));
    return r;
}
__device__ __forceinline__ void st_cluster_b64(u32 addr, u64 v) {
    asm volatile("st.shared::cluster.b64 [%0],%1;" :: "r"(addr), "l"(v) : "memory");
}
__device__ __forceinline__ void mbar_init(u32 addr, u32 cnt) {
    asm volatile("mbarrier.init.shared.b64 [%0],%1;" :: "r"(addr), "r"(cnt) : "memory");
}
__device__ __forceinline__ void mbar_arrive_local(u32 addr) {
    asm volatile("mbarrier.arrive.release.cta.shared::cta.b64 _,[%0];" :: "r"(addr) : "memory");
}
__device__ __forceinline__ void mbar_arrive_remote(u32 remote_addr) {
    asm volatile("mbarrier.arrive.release.cluster.shared::cluster.b64 _,[%0];"
                 :: "r"(remote_addr) : "memory");
}
__device__ __forceinline__ void mbar_wait(u32 addr, u32 parity) {
    asm volatile(
        "{\n\t.reg .pred P;\n\t"
        "WL_%=:\n\t"
        "mbarrier.try_wait.parity.acquire.cluster.shared::cta.b64 P,[%0],%1,0x989680;\n\t"
        "@P bra.uni WD_%=;\n\t"
        "bra.uni WL_%=;\n\t"
        "WD_%=:\n\t}"
        :: "r"(addr), "r"(parity) : "memory");
}
#define CLUSTER_SYNC() do {                                          \
    asm volatile("barrier.cluster.arrive.aligned;" ::: "memory");    \
    asm volatile("barrier.cluster.wait.aligned;" ::: "memory");      \
} while (0)

// ============================================================================
// Kernel 1: FPS, cluster of 4 CTAs per batch; 4096 pts/CTA, 8/thread,
// coordinates fully register-resident.  Lean argmax: redux(dist) +
// redux(revidx among matchers) per warp -> one u64 key per warp -> one
// barrier -> flat 16-key max.  Winner thread pushes {key,xyz} to all 4
// ranks via DSMEM + mbar (count=4); one parity wait per iteration.
// Key = (dist_bits<<32) | (16383-idx): float order on top bits (d>=0),
// lowest-index-on-tie via reversed index.  Bit-exact vs jnp.argmax.
// ============================================================================
#define CSZ   4
#define LPTS  (NN / CSZ)     /* 4096 */
#define FT    512
#define FPPT  (LPTS / FT)    /* 8 */

__global__ void __launch_bounds__(FT, 1) __cluster_dims__(CSZ, 1, 1)
fps_kernel(const float* __restrict__ pts, float* __restrict__ out)
{
    __shared__ __align__(16) u64 s_wkey[FT / 32];
    __shared__ u64  s_cand[2][CSZ][3];       // [slot][rank]{key, xy, z}
    __shared__ __align__(8) u64 s_mbar[1];
    __shared__ float4 s_hist[NFPS];

    const int rank = blockIdx.x, b = blockIdx.y, t = threadIdx.x;
    const int lane = t & 31, warp = t >> 5;
    const float* base = pts + (size_t)b * 3 * NN;
    const int g0 = rank * LPTS;
    const u32 mbar_a = smem_u32(&s_mbar[0]);

    if (t == 0) mbar_init(mbar_a, CSZ);
    __syncthreads();
    CLUSTER_SYNC();   // all mbar inits visible before any remote arrive

    // my 4096 points in registers, packed pairs (slots 2j, 2j+1)
    u64 rx[FPPT / 2], ry[FPPT / 2], rz[FPPT / 2];
#pragma unroll
    for (int j = 0; j < FPPT / 2; j++) {
        const int n0 = g0 + t + (2 * j) * FT, n1 = n0 + FT;
        rx[j] = pack2(base[n0], base[n1]);
        ry[j] = pack2(base[NN + n0], base[NN + n1]);
        rz[j] = pack2(base[2 * NN + n0], base[2 * NN + n1]);
    }
    float dist[FPPT];
#pragma unroll
    for (int k = 0; k < FPPT; k++) dist[k] = 1e10f;

    float cx = base[0], cy = base[NN], cz = base[2 * NN];
    int cur = 0;

    for (int i = 0; i < NFPS; i++) {
        if (rank == 0 && t == 0)
            s_hist[i] = make_float4(cx, cy, cz, __int_as_float(cur));

        const u64 nx = pack2(-cx, -cx), ny = pack2(-cy, -cy), nz = pack2(-cz, -cz);
        float v0 = -1.0f, v1 = -1.0f;
#pragma unroll
        for (int j = 0; j < FPPT / 2; j++) {
            u64 dx = add2(rx[j], nx), dy = add2(ry[j], ny), dz = add2(rz[j], nz);
            u64 s = mul2(dx, dx); s = fma2(dy, dy, s); s = fma2(dz, dz, s);
            float a, c; unpack2(s, a, c);
            float d0 = fminf(dist[2 * j], a), d1 = fminf(dist[2 * j + 1], c);
            dist[2 * j] = d0; dist[2 * j + 1] = d1;
            v0 = fmaxf(v0, d0); v1 = fmaxf(v1, d1);
        }
        const float vmax = fmaxf(v0, v1);

        // warp argmax: max dist, then max reversed index among matchers
        const u32 wm = __reduce_max_sync(0xffffffffu, __float_as_uint(vmax));
        u32 rev = 0u;
        if (__float_as_uint(vmax) == wm) {
            bool got = false;
#pragma unroll
            for (int k = 0; k < FPPT; k++) {
                if (!got && __float_as_uint(dist[k]) == wm) {
                    rev = 16383u - (u32)(g0 + t + k * FT);   // first match = smallest idx
                    got = true;
                }
            }
        }
        rev = __reduce_max_sync(0xffffffffu, rev);
        if (lane == 0) s_wkey[warp] = ((u64)wm << 32) | (u64)rev;
        __syncthreads();                               // (single barrier)

        // flat block max over 16 warp keys (8 x 16B broadcast loads)
        u64 bk;
        {
            const ulonglong2* p = (const ulonglong2*)s_wkey;
            ulonglong2 q = p[0];
            bk = umax64(q.x, q.y);
#pragma unroll
            for (int w = 1; w < FT / 64; w++) {
                q = p[w];
                bk = umax64(bk, umax64(q.x, q.y));
            }
        }
        const int slot = i & 1;
        const int widx = 16383 - (int)(bk & 0xffffffffu);
        const int l = widx - g0;

        if (l >= 0 && l < LPTS && (l & (FT - 1)) == t) {
            // I own the block winner: pull coords from my registers
            const int k = l >> 9, jj = k >> 1, hi = k & 1;
            float wx = 0.f, wy = 0.f, wz = 0.f;
#pragma unroll
            for (int j = 0; j < FPPT / 2; j++) {
                if (j == jj) {
                    float a, c;
                    unpack2(rx[j], a, c); wx = hi ? c : a;
                    unpack2(ry[j], a, c); wy = hi ? c : a;
                    unpack2(rz[j], a, c); wz = hi ? c : a;
                }
            }
            const u64 xy = (u64)__float_as_uint(wx) | ((u64)__float_as_uint(wy) << 32);
            const u64 zz = (u64)__float_as_uint(wz);
#pragma unroll
            for (int r = 0; r < CSZ; r++) {
                if (r == rank) {
                    s_cand[slot][rank][0] = bk;
                    s_cand[slot][rank][1] = xy;
                    s_cand[slot][rank][2] = zz;
                    mbar_arrive_local(mbar_a);
                } else {
                    const u32 ra = mapa_rank(smem_u32(&s_cand[slot][rank][0]), (u32)r);
                    st_cluster_b64(ra, bk);
                    st_cluster_b64(ra + 8, xy);
                    st_cluster_b64(ra + 16, zz);
                    mbar_arrive_remote(mapa_rank(mbar_a, (u32)r));
                }
            }
        }

        mbar_wait(mbar_a, (u32)(i & 1));               // all 4 candidates visible

        u64 kw = s_cand[slot][0][0];
        int w = 0;
#pragma unroll
        for (int r = 1; r < CSZ; r++) {
            const u64 k = s_cand[slot][r][0];
            if (k > kw) { kw = k; w = r; }
        }
        float a, c;
        unpack2(s_cand[slot][w][1], a, c);
        cx = a; cy = c;
        cz = __uint_as_float((u32)s_cand[slot][w][2]);
        cur = 16383 - (int)(kw & 0xffffffffu);
    }

    if (rank == 0) {
        __syncthreads();
        if (t < NFPS) {
            const float4 h = s_hist[t];
            const int idx = __float_as_int(h.w);
            g_fps_idx[b][t] = idx;
            float* o = out + ((size_t)b * 1536 + 1024 + t) * 3;
            o[0] = h.x; o[1] = h.y; o[2] = h.z;
        }
    }
    CLUSTER_SYNC();   // no CTA exits while peer stores may be in flight
}

// ============================================================================
// Kernel 2: per-(batch, anchor) ball count.  grid = (NREG, BB)
// ============================================================================
__global__ void count_kernel(const float* __restrict__ pts)
{
    const int a = blockIdx.x, b = blockIdx.y;
    const int t = threadIdx.x;
    const float* base = pts + (size_t)b * 3 * NN;
    const int aidx = g_fps_idx[b][a];
    const float ax = base[aidx], ay = base[NN + aidx], az = base[2 * NN + aidx];
    const float a2 = ax * ax + ay * ay + az * az;

    int cnt = 0;
    for (int n = t; n < NN; n += 256) {
        float x = base[n], y = base[NN + n], z = base[2 * NN + n];
        float dot = ax * x + ay * y + az * z;
        float p2 = x * x + y * y + z * z;
        float d = (-2.0f * dot + a2) + p2;
        cnt += (d < R2C) ? 1 : 0;
    }
    __shared__ int s_c[8];
#pragma unroll
    for (int o = 16; o > 0; o >>= 1) cnt += __shfl_xor_sync(0xffffffffu, cnt, o);
    if ((t & 31) == 0) s_c[t >> 5] = cnt;
    __syncthreads();
    if (t == 0) {
        int s = 0;
#pragma unroll
        for (int w = 0; w < 8; w++) s += s_c[w];
        g_counts[b][a] = min(s, 1000);
    }
}

// ============================================================================
// Kernel 3: top-4 anchors by count (ties -> lower index).  grid = BB
// ============================================================================
__global__ void top4_kernel()
{
    const int b = blockIdx.x;
    if (threadIdx.x != 0) return;
    int cnts[NREG];
    for (int a = 0; a < NREG; a++) cnts[a] = g_counts[b][a];
    for (int j = 0; j < TOPK; j++) {
        int best = -1, bi = 0;
        for (int a = 0; a < NREG; a++)
            if (cnts[a] > best) { best = cnts[a]; bi = a; }
        g_top4[b][j] = g_fps_idx[b][bi];
        cnts[bi] = -2;
    }
}

// ============================================================================
// Kernel 4: 128-NN per (query, batch).  grid = (TOPK, BB)  (validated, 54us)
// ============================================================================
#define KT   512
#define KPPT 32

__global__ void __launch_bounds__(KT, 1)
knn_kernel(const float* __restrict__ pts, float* __restrict__ out)
{
    const int q = blockIdx.x, b = blockIdx.y;
    const int t = threadIdx.x, lane = t & 31, warp = t >> 5;
    const float* base = pts + (size_t)b * 3 * NN;
    __shared__ u32 s_wmin[KT / 32];
    __shared__ u32 s_minv;
    __shared__ int s_tid[2];
    __shared__ int s_win[NB];

    if (t == 0) { s_tid[0] = 0x7fffffff; s_tid[1] = 0x7fffffff; }

    const int qidx = g_top4[b][q];
    const float qx = base[qidx], qy = base[NN + qidx], qz = base[2 * NN + qidx];
    const float q2 = qx * qx + qy * qy + qz * qz;

    const int p0 = t * KPPT;
    u32 u[KPPT];

#define DPT(X, Y, Z, K) {                                                   \
        float dot = qx * (X) + qy * (Y) + qz * (Z);                         \
        float p2 = (X) * (X) + (Y) * (Y) + (Z) * (Z);                       \
        float d = (-2.0f * dot + q2) + p2;                                  \
        u32 ub = __float_as_uint(d);                                        \
        ub = (ub & 0x80000000u) ? ~ub : (ub | 0x80000000u);                 \
        u[K] = ub; }

#pragma unroll
    for (int g = 0; g < 8; g++) {
        const float4 x4 = *(const float4*)&base[p0 + 4 * g];
        const float4 y4 = *(const float4*)&base[NN + p0 + 4 * g];
        const float4 z4 = *(const float4*)&base[2 * NN + p0 + 4 * g];
        DPT(x4.x, y4.x, z4.x, 4 * g + 0)
        DPT(x4.y, y4.y, z4.y, 4 * g + 1)
        DPT(x4.z, y4.z, z4.z, 4 * g + 2)
        DPT(x4.w, y4.w, z4.w, 4 * g + 3)
    }
#undef DPT

    u32 gmin[4];
#pragma unroll
    for (int g = 0; g < 4; g++) {
        u32 m = u[8 * g];
#pragma unroll
        for (int k = 1; k < 8; k++) m = min(m, u[8 * g + k]);
        gmin[g] = m;
    }
    u32 tmin = min(min(gmin[0], gmin[1]), min(gmin[2], gmin[3]));
    __syncthreads();

    for (int j = 0; j < NB; j++) {
        u32 wm = __reduce_min_sync(0xffffffffu, tmin);
        if (lane == 0) s_wmin[warp] = wm;
        __syncthreads();
        if (warp == 0) {
            u32 v = (lane < KT / 32) ? s_wmin[lane] : 0xffffffffu;
            v = __reduce_min_sync(0xffffffffu, v);
            if (lane == 0) s_minv = v;
        }
        __syncthreads();
        const u32 m = s_minv;
        const int slot = j & 1;
        if (tmin == m) atomicMin(&s_tid[slot], t);
        if (t == 0) s_tid[slot ^ 1] = 0x7fffffff;
        __syncthreads();
        if (t == s_tid[slot]) {
            bool found = false;
#pragma unroll
            for (int g = 0; g < 4; g++) {
                if (!found && gmin[g] == m) {
                    bool f2 = false;
#pragma unroll
                    for (int k = 0; k < 8; k++) {
                        if (!f2 && u[8 * g + k] == m) {
                            u[8 * g + k] = 0xffffffffu;
                            s_win[j] = p0 + 8 * g + k;
                            f2 = true;
                        }
                    }
                    u32 nm = u[8 * g];
#pragma unroll
                    for (int k = 1; k < 8; k++) nm = min(nm, u[8 * g + k]);
                    gmin[g] = nm;
                    found = true;
                }
            }
            tmin = min(min(gmin[0], gmin[1]), min(gmin[2], gmin[3]));
        }
    }

    __syncthreads();
    if (t < NB) {
        const int win = s_win[t];
        const float x = base[win], y = base[NN + win], z = base[2 * NN + win];
        const size_t r = (size_t)b * 1536 + (size_t)q * NB + t;
        float* o1 = out + r * 3;
        o1[0] = x; o1[1] = y; o1[2] = z;
        float* o2 = out + (r + 512) * 3;
        o2[0] = x; o2[1] = y; o2[2] = z;
    }
}

// ============================================================================
extern "C" void kernel_launch(void* const* d_in, const int* in_sizes, int n_in,
                              void* d_out, int out_size)
{
    const float* pts = (const float*)d_in[0];
    float* out = (float*)d_out;

    fps_kernel<<<dim3(CSZ, BB), FT>>>(pts, out);
    count_kernel<<<dim3(NREG, BB), 256>>>(pts);
    top4_kernel<<<BB, 32>>>();
    knn_kernel<<<dim3(TOPK, BB), KT>>>(pts, out);
}

// round 7
// speedup vs baseline: 1.1666x; 1.1666x over previous
#include <cuda_runtime.h>

#define BB    16
#define NN    16384
#define NFPS  512
#define NREG  50
#define TOPK  4
#define NB    128
#define R2C   0.16f

typedef unsigned int u32;
typedef unsigned long long u64;

__device__ int g_fps_idx[BB][NFPS];
__device__ int g_counts[BB][NREG];
__device__ int g_top4[BB][TOPK];

// ---- packed f32x2 helpers (sm_100a) ---------------------------------------
__device__ __forceinline__ u64 pack2(float lo, float hi) {
    u64 r; asm("mov.b64 %0,{%1,%2};" : "=l"(r) : "f"(lo), "f"(hi)); return r;
}
__device__ __forceinline__ void unpack2(u64 v, float& lo, float& hi) {
    asm("mov.b64 {%0,%1},%2;" : "=f"(lo), "=f"(hi) : "l"(v));
}
__device__ __forceinline__ u64 add2(u64 a, u64 b) {
    u64 r; asm("add.rn.f32x2 %0,%1,%2;" : "=l"(r) : "l"(a), "l"(b)); return r;
}
__device__ __forceinline__ u64 mul2(u64 a, u64 b) {
    u64 r; asm("mul.rn.f32x2 %0,%1,%2;" : "=l"(r) : "l"(a), "l"(b)); return r;
}
__device__ __forceinline__ u64 fma2(u64 a, u64 b, u64 c) {
    u64 r; asm("fma.rn.f32x2 %0,%1,%2,%3;" : "=l"(r) : "l"(a), "l"(b), "l"(c)); return r;
}
__device__ __forceinline__ u64 umax64(u64 a, u64 b) { return a > b ? a : b; }
__device__ __forceinline__ u64 umin64(u64 a, u64 b) { return a < b ? a : b; }

// ---- cluster / mbarrier helpers --------------------------------------------
__device__ __forceinline__ u32 smem_u32(const void* p) {
    return (u32)__cvta_generic_to_shared(p);
}
__device__ __forceinline__ u32 mapa_rank(u32 addr, u32 rank) {
    u32 r;
    asm("mapa.shared::cluster.u32 %0,%1,%2;" : "=r"(r) : "r"(addr), "r"(rank));
    return r;
}
__device__ __forceinline__ void st_cluster_b64(u32 addr, u64 v) {
    asm volatile("st.shared::cluster.b64 [%0],%1;" :: "r"(addr), "l"(v) : "memory");
}
__device__ __forceinline__ void mbar_init(u32 addr, u32 cnt) {
    asm volatile("mbarrier.init.shared.b64 [%0],%1;" :: "r"(addr), "r"(cnt) : "memory");
}
__device__ __forceinline__ void mbar_arrive_local(u32 addr) {
    asm volatile("mbarrier.arrive.release.cta.shared::cta.b64 _,[%0];" :: "r"(addr) : "memory");
}
__device__ __forceinline__ void mbar_arrive_remote(u32 remote_addr) {
    asm volatile("mbarrier.arrive.release.cluster.shared::cluster.b64 _,[%0];"
                 :: "r"(remote_addr) : "memory");
}
__device__ __forceinline__ void mbar_wait(u32 addr, u32 parity) {
    asm volatile(
        "{\n\t.reg .pred P;\n\t"
        "WL_%=:\n\t"
        "mbarrier.try_wait.parity.acquire.cluster.shared::cta.b64 P,[%0],%1,0x989680;\n\t"
        "@P bra.uni WD_%=;\n\t"
        "bra.uni WL_%=;\n\t"
        "WD_%=:\n\t}"
        :: "r"(addr), "r"(parity) : "memory");
}
#define CLUSTER_SYNC() do {                                          \
    asm volatile("barrier.cluster.arrive.aligned;" ::: "memory");    \
    asm volatile("barrier.cluster.wait.aligned;" ::: "memory");      \
} while (0)

// ============================================================================
// Kernel 1: FPS, cluster of 2 CTAs per batch; 8192 pts/CTA, 16/thread,
// coordinates fully register-resident.  Lean argmax: 2x redux per warp,
// owner lane pre-extracts coords and stores {key,xyz}; ONE barrier; flat
// 16-key max; 3 fixed pusher threads forward the winning candidate to both
// CTAs in parallel; mbar count=6 (3 local + 3 remote arrives); one parity
// wait.  Key = (dist_bits<<32)|(16383-idx): bit-exact vs jnp.argmax.
// ============================================================================
#define CSZ   2
#define LPTS  (NN / CSZ)     /* 8192 */
#define FT    512
#define FPPT  (LPTS / FT)    /* 16 */

__global__ void __launch_bounds__(FT, 1) __cluster_dims__(CSZ, 1, 1)
fps_kernel(const float* __restrict__ pts, float* __restrict__ out)
{
    __shared__ __align__(16) u64 s_wkey[2][FT / 32];
    __shared__ __align__(16) u64 s_wcand[FT / 32][3];   // {key, xy, z}
    __shared__ u64  s_cand[2][CSZ][3];                  // [slot][rank]{key, xy, z}
    __shared__ __align__(8) u64 s_mbar[1];
    __shared__ float4 s_hist[NFPS];

    const int rank = blockIdx.x, b = blockIdx.y, t = threadIdx.x;
    const int warp = t >> 5;
    const float* base = pts + (size_t)b * 3 * NN;
    const int g0 = rank * LPTS;
    const u32 mbar_a = smem_u32(&s_mbar[0]);
    const u32 peer = (u32)(rank ^ 1);

    if (t == 0) mbar_init(mbar_a, 6);
    __syncthreads();
    CLUSTER_SYNC();   // peer mbar init visible before any remote arrive

    // my 8192 points in registers, packed pairs (slots 2j, 2j+1)
    u64 rx[FPPT / 2], ry[FPPT / 2], rz[FPPT / 2];
#pragma unroll
    for (int j = 0; j < FPPT / 2; j++) {
        const int n0 = g0 + t + (2 * j) * FT, n1 = n0 + FT;
        rx[j] = pack2(base[n0], base[n1]);
        ry[j] = pack2(base[NN + n0], base[NN + n1]);
        rz[j] = pack2(base[2 * NN + n0], base[2 * NN + n1]);
    }
    float dist[FPPT];
#pragma unroll
    for (int k = 0; k < FPPT; k++) dist[k] = 1e10f;

    float cx = base[0], cy = base[NN], cz = base[2 * NN];
    int cur = 0;

    for (int i = 0; i < NFPS; i++) {
        if (rank == 0 && t == 0)
            s_hist[i] = make_float4(cx, cy, cz, __int_as_float(cur));

        const u64 nx = pack2(-cx, -cx), ny = pack2(-cy, -cy), nz = pack2(-cz, -cz);
        float v0 = -1.0f, v1 = -1.0f;
#pragma unroll
        for (int j = 0; j < FPPT / 2; j++) {
            u64 dx = add2(rx[j], nx), dy = add2(ry[j], ny), dz = add2(rz[j], nz);
            u64 s = mul2(dx, dx); s = fma2(dy, dy, s); s = fma2(dz, dz, s);
            float a, c; unpack2(s, a, c);
            float d0 = fminf(dist[2 * j], a), d1 = fminf(dist[2 * j + 1], c);
            dist[2 * j] = d0; dist[2 * j + 1] = d1;
            v0 = fmaxf(v0, d0); v1 = fmaxf(v1, d1);
        }
        const float vmax = fmaxf(v0, v1);
        const int par = i & 1;

        // warp argmax: max dist bits, then max reversed index among matchers
        const u32 wm = __reduce_max_sync(0xffffffffu, __float_as_uint(vmax));
        u32 rev = 0u;
        int k0 = -1;
        if (__float_as_uint(vmax) == wm) {
#pragma unroll
            for (int k = 0; k < FPPT; k++)
                if (k0 < 0 && __float_as_uint(dist[k]) == wm) k0 = k;
            rev = 16383u - (u32)(g0 + t + k0 * FT);
        }
        const u32 wrev = __reduce_max_sync(0xffffffffu, rev);

        if (k0 >= 0 && rev == wrev) {
            // owner lane of this warp: pre-extract coords, publish key+cand
            const int jj = k0 >> 1, hi = k0 & 1;
            float wx = 0.f, wy = 0.f, wz = 0.f;
#pragma unroll
            for (int j = 0; j < FPPT / 2; j++) {
                if (j == jj) {
                    float a, c;
                    unpack2(rx[j], a, c); wx = hi ? c : a;
                    unpack2(ry[j], a, c); wy = hi ? c : a;
                    unpack2(rz[j], a, c); wz = hi ? c : a;
                }
            }
            const u64 key = ((u64)wm << 32) | (u64)wrev;
            s_wkey[par][warp] = key;
            s_wcand[warp][0] = key;
            s_wcand[warp][1] = (u64)__float_as_uint(wx) | ((u64)__float_as_uint(wy) << 32);
            s_wcand[warp][2] = (u64)__float_as_uint(wz);
        }
        __syncthreads();                        // single barrier per iteration

        // flat block max over 16 warp keys (broadcast 16B loads)
        u64 bk;
        {
            const ulonglong2* p = (const ulonglong2*)s_wkey[par];
            ulonglong2 q = p[0];
            bk = umax64(q.x, q.y);
#pragma unroll
            for (int w = 1; w < FT / 64; w++) {
                q = p[w];
                bk = umax64(bk, umax64(q.x, q.y));
            }
        }

        if (t < 3) {
            // forward my CTA's candidate (component t) to both CTAs
            const int l = (16383 - (int)(bk & 0xffffffffu)) - g0;   // local idx
            const int w = (l & (FT - 1)) >> 5;                      // winning warp
            const u64 val = s_wcand[w][t];
            s_cand[par][rank][t] = val;
            st_cluster_b64(mapa_rank(smem_u32(&s_cand[par][rank][t]), peer), val);
            mbar_arrive_local(mbar_a);
            mbar_arrive_remote(mapa_rank(mbar_a, peer));
        }

        mbar_wait(mbar_a, (u32)par);            // both candidates visible

        const u64 k0c = s_cand[par][0][0], k1c = s_cand[par][1][0];
        const int w = (k1c > k0c) ? 1 : 0;
        const u64 kw = w ? k1c : k0c;
        float a, c;
        unpack2(s_cand[par][w][1], a, c);
        cx = a; cy = c;
        cz = __uint_as_float((u32)s_cand[par][w][2]);
        cur = 16383 - (int)(kw & 0xffffffffu);
    }

    if (rank == 0) {
        __syncthreads();
        if (t < NFPS) {
            const float4 h = s_hist[t];
            const int idx = __float_as_int(h.w);
            g_fps_idx[b][t] = idx;
            float* o = out + ((size_t)b * 1536 + 1024 + t) * 3;
            o[0] = h.x; o[1] = h.y; o[2] = h.z;
        }
    }
    CLUSTER_SYNC();   // no CTA exits while peer stores may be in flight
}

// ============================================================================
// Kernel 2: per-(batch, anchor) ball count.  grid = (NREG, BB)
// ============================================================================
__global__ void count_kernel(const float* __restrict__ pts)
{
    const int a = blockIdx.x, b = blockIdx.y;
    const int t = threadIdx.x;
    const float* base = pts + (size_t)b * 3 * NN;
    const int aidx = g_fps_idx[b][a];
    const float ax = base[aidx], ay = base[NN + aidx], az = base[2 * NN + aidx];
    const float a2 = ax * ax + ay * ay + az * az;

    int cnt = 0;
    for (int n = t; n < NN; n += 256) {
        float x = base[n], y = base[NN + n], z = base[2 * NN + n];
        float dot = ax * x + ay * y + az * z;
        float p2 = x * x + y * y + z * z;
        float d = (-2.0f * dot + a2) + p2;
        cnt += (d < R2C) ? 1 : 0;
    }
    __shared__ int s_c[8];
#pragma unroll
    for (int o = 16; o > 0; o >>= 1) cnt += __shfl_xor_sync(0xffffffffu, cnt, o);
    if ((t & 31) == 0) s_c[t >> 5] = cnt;
    __syncthreads();
    if (t == 0) {
        int s = 0;
#pragma unroll
        for (int w = 0; w < 8; w++) s += s_c[w];
        g_counts[b][a] = min(s, 1000);
    }
}

// ============================================================================
// Kernel 3: top-4 anchors by count (ties -> lower index).  grid = BB
// ============================================================================
__global__ void top4_kernel()
{
    const int b = blockIdx.x;
    if (threadIdx.x != 0) return;
    int cnts[NREG];
    for (int a = 0; a < NREG; a++) cnts[a] = g_counts[b][a];
    for (int j = 0; j < TOPK; j++) {
        int best = -1, bi = 0;
        for (int a = 0; a < NREG; a++)
            if (cnts[a] > best) { best = cnts[a]; bi = a; }
        g_top4[b][j] = g_fps_idx[b][bi];
        cnts[bi] = -2;
    }
}

// ============================================================================
// Kernel 4: 128-NN per (query, batch).  grid = (TOPK, BB), 512 thr x 32 pts.
// Lean single-barrier extraction: warp key = (dist<<32)|tid (tie -> lower
// thread -> lower index; within-thread first slot = lowest index), flat
// 16-key min, winner thread updates its cached group mins locally.
// ============================================================================
#define KT   512
#define KPPT 32

__global__ void __launch_bounds__(KT, 1)
knn_kernel(const float* __restrict__ pts, float* __restrict__ out)
{
    const int q = blockIdx.x, b = blockIdx.y;
    const int t = threadIdx.x, lane = t & 31, warp = t >> 5;
    const float* base = pts + (size_t)b * 3 * NN;
    __shared__ __align__(16) u64 s_wkey[2][KT / 32];
    __shared__ int s_win[NB];

    const int qidx = g_top4[b][q];
    const float qx = base[qidx], qy = base[NN + qidx], qz = base[2 * NN + qidx];
    const float q2 = qx * qx + qy * qy + qz * qz;

    const int p0 = t * KPPT;
    u32 u[KPPT];

#define DPT(X, Y, Z, K) {                                                   \
        float dot = qx * (X) + qy * (Y) + qz * (Z);                         \
        float p2 = (X) * (X) + (Y) * (Y) + (Z) * (Z);                       \
        float d = (-2.0f * dot + q2) + p2;                                  \
        u32 ub = __float_as_uint(d);                                        \
        ub = (ub & 0x80000000u) ? ~ub : (ub | 0x80000000u);                 \
        u[K] = ub; }

#pragma unroll
    for (int g = 0; g < 8; g++) {
        const float4 x4 = *(const float4*)&base[p0 + 4 * g];
        const float4 y4 = *(const float4*)&base[NN + p0 + 4 * g];
        const float4 z4 = *(const float4*)&base[2 * NN + p0 + 4 * g];
        DPT(x4.x, y4.x, z4.x, 4 * g + 0)
        DPT(x4.y, y4.y, z4.y, 4 * g + 1)
        DPT(x4.z, y4.z, z4.z, 4 * g + 2)
        DPT(x4.w, y4.w, z4.w, 4 * g + 3)
    }
#undef DPT

    u32 gmin[4];
#pragma unroll
    for (int g = 0; g < 4; g++) {
        u32 m = u[8 * g];
#pragma unroll
        for (int k = 1; k < 8; k++) m = min(m, u[8 * g + k]);
        gmin[g] = m;
    }
    u32 tmin = min(min(gmin[0], gmin[1]), min(gmin[2], gmin[3]));
    __syncthreads();

    for (int j = 0; j < NB; j++) {
        const int par = j & 1;
        const u32 wm = __reduce_min_sync(0xffffffffu, tmin);
        u32 idxt = (tmin == wm) ? (u32)t : 0xffffffffu;
        idxt = __reduce_min_sync(0xffffffffu, idxt);
        if (lane == 0) s_wkey[par][warp] = ((u64)wm << 32) | (u64)idxt;
        __syncthreads();                        // single barrier per iteration

        u64 bk;
        {
            const ulonglong2* p = (const ulonglong2*)s_wkey[par];
            ulonglong2 qq = p[0];
            bk = umin64(qq.x, qq.y);
#pragma unroll
            for (int w = 1; w < KT / 64; w++) {
                qq = p[w];
                bk = umin64(bk, umin64(qq.x, qq.y));
            }
        }
        const u32 m = (u32)(bk >> 32);
        if (t == (int)(u32)(bk & 0xffffffffu)) {
            bool found = false;
#pragma unroll
            for (int g = 0; g < 4; g++) {
                if (!found && gmin[g] == m) {
                    bool f2 = false;
#pragma unroll
                    for (int k = 0; k < 8; k++) {
                        if (!f2 && u[8 * g + k] == m) {
                            u[8 * g + k] = 0xffffffffu;
                            s_win[j] = p0 + 8 * g + k;
                            f2 = true;
                        }
                    }
                    u32 nm = u[8 * g];
#pragma unroll
                    for (int k = 1; k < 8; k++) nm = min(nm, u[8 * g + k]);
                    gmin[g] = nm;
                    found = true;
                }
            }
            tmin = min(min(gmin[0], gmin[1]), min(gmin[2], gmin[3]));
        }
    }

    __syncthreads();
    if (t < NB) {
        const int win = s_win[t];
        const float x = base[win], y = base[NN + win], z = base[2 * NN + win];
        const size_t r = (size_t)b * 1536 + (size_t)q * NB + t;
        float* o1 = out + r * 3;
        o1[0] = x; o1[1] = y; o1[2] = z;
        float* o2 = out + (r + 512) * 3;
        o2[0] = x; o2[1] = y; o2[2] = z;
    }
}

// ============================================================================
extern "C" void kernel_launch(void* const* d_in, const int* in_sizes, int n_in,
                              void* d_out, int out_size)
{
    const float* pts = (const float*)d_in[0];
    float* out = (float*)d_out;

    fps_kernel<<<dim3(CSZ, BB), FT>>>(pts, out);
    count_kernel<<<dim3(NREG, BB), 256>>>(pts);
    top4_kernel<<<BB, 32>>>();
    knn_kernel<<<dim3(TOPK, BB), KT>>>(pts, out);
}